// round 7
// baseline (speedup 1.0000x reference)
#include <cuda_runtime.h>
#include <math.h>

// ---------------------------------------------------------------------------
// Problem constants
// ---------------------------------------------------------------------------
#define DIMC   768
#define DEPTHC 8
#define HEADSC 12
#define DHC    64
#define DFFC   2048
#define BC     2
#define TC     32
#define SC     256
#define NTOK   (BC*TC*SC)          // 16384 tokens
#define SMEM_SP (2*SC*DHC*(int)sizeof(float))  // 128 KB for space attention K+V
// FF-in fused kernel dynamic smem: As+Bs (4096 floats) + per-thread gelu stash (256*65)
#define FF_SMEM ((4096 + 256*65)*(int)sizeof(float))

// ---------------------------------------------------------------------------
// Static device scratch (allocation-free rule: __device__ globals)
// ---------------------------------------------------------------------------
__device__ float g_x  [NTOK*DIMC];
__device__ float g_tn [NTOK*DIMC];
__device__ float g_q  [NTOK*DIMC];
__device__ float g_k  [NTOK*DIMC];
__device__ float g_v  [NTOK*DIMC];
__device__ float g_o  [NTOK*DIMC];
__device__ float g_rv [NTOK*DIMC];
__device__ float g_mix [NTOK*HEADSC];
__device__ float g_gate[NTOK*HEADSC];
__device__ float g_act[NTOK*DFFC];

// ---------------------------------------------------------------------------
// RMSNorm: out = x * rsqrt(mean(x^2)+eps) * w   (one block per token, 256 thr)
// ---------------------------------------------------------------------------
__global__ void rmsnorm_kernel(const float* __restrict__ x,
                               const float* __restrict__ w,
                               float* __restrict__ out)
{
    int tok = blockIdx.x;
    const float* xp = x + (size_t)tok * DIMC;
    int t = threadIdx.x;
    float v0 = xp[t], v1 = xp[t+256], v2 = xp[t+512];
    float ss = v0*v0 + v1*v1 + v2*v2;

    __shared__ float sh[8];
    int lane = t & 31, wid = t >> 5;
    #pragma unroll
    for (int off = 16; off; off >>= 1) ss += __shfl_down_sync(0xffffffffu, ss, off);
    if (lane == 0) sh[wid] = ss;
    __syncthreads();
    if (wid == 0) {
        float v = (lane < 8) ? sh[lane] : 0.f;
        #pragma unroll
        for (int off = 16; off; off >>= 1) v += __shfl_down_sync(0xffffffffu, v, off);
        if (lane == 0) sh[0] = v;
    }
    __syncthreads();
    float scale = rsqrtf(sh[0] * (1.0f/DIMC) + 1e-6f);
    float* op = out + (size_t)tok * DIMC;
    op[t]     = v0 * scale * w[t];
    op[t+256] = v1 * scale * w[t+256];
    op[t+512] = v2 * scale * w[t+512];
}

// ---------------------------------------------------------------------------
// SGEMM core: fills acc[8][8] for a 128x128 tile of A[M,K]@B[K,N].
// K-step 8, 256 threads, 8x8 microtile, float4, register-staged double
// buffering, one __syncthreads per K-step. Requires K%8==0, N%128==0.
// NOTE: no trailing sync — caller must __syncthreads() before reusing As/Bs.
// ---------------------------------------------------------------------------
__device__ __forceinline__ void sgemm_core(
    const float* __restrict__ A, const float* __restrict__ B,
    int N, int K, int bm, int bn,
    float (*As)[8][128], float (*Bs)[8][128], float acc[8][8])
{
    int tid = threadIdx.x;
    int aRow = tid >> 1;            // 0..127
    int aK   = (tid & 1) * 4;       // 0 or 4
    int bRow = tid >> 5;            // 0..7
    int bCol = (tid & 31) * 4;      // 0..124
    int mr = (tid >> 4) * 8;        // 0..120
    int nc = (tid & 15) * 8;        // 0..120

    #pragma unroll
    for (int i = 0; i < 8; i++)
        #pragma unroll
        for (int j = 0; j < 8; j++) acc[i][j] = 0.f;

    // preload tile 0
    {
        float4 a4 = *reinterpret_cast<const float4*>(&A[(size_t)(bm + aRow) * K + aK]);
        As[0][aK+0][aRow] = a4.x;
        As[0][aK+1][aRow] = a4.y;
        As[0][aK+2][aRow] = a4.z;
        As[0][aK+3][aRow] = a4.w;
        float4 b4 = *reinterpret_cast<const float4*>(&B[(size_t)bRow * N + bn + bCol]);
        *reinterpret_cast<float4*>(&Bs[0][bRow][bCol]) = b4;
    }
    __syncthreads();

    int buf = 0;
    for (int k0 = 0; k0 < K; k0 += 8) {
        bool has_next = (k0 + 8) < K;
        float4 a4n, b4n;
        if (has_next) {
            a4n = *reinterpret_cast<const float4*>(&A[(size_t)(bm + aRow) * K + k0 + 8 + aK]);
            b4n = *reinterpret_cast<const float4*>(&B[(size_t)(k0 + 8 + bRow) * N + bn + bCol]);
        }

        #pragma unroll
        for (int kk = 0; kk < 8; kk++) {
            float4 a0 = *reinterpret_cast<const float4*>(&As[buf][kk][mr]);
            float4 a1 = *reinterpret_cast<const float4*>(&As[buf][kk][mr+4]);
            float4 b0 = *reinterpret_cast<const float4*>(&Bs[buf][kk][nc]);
            float4 b1 = *reinterpret_cast<const float4*>(&Bs[buf][kk][nc+4]);
            float av[8] = {a0.x,a0.y,a0.z,a0.w,a1.x,a1.y,a1.z,a1.w};
            float bv[8] = {b0.x,b0.y,b0.z,b0.w,b1.x,b1.y,b1.z,b1.w};
            #pragma unroll
            for (int i = 0; i < 8; i++)
                #pragma unroll
                for (int j = 0; j < 8; j++)
                    acc[i][j] = fmaf(av[i], bv[j], acc[i][j]);
        }

        if (has_next) {
            int nb = buf ^ 1;
            As[nb][aK+0][aRow] = a4n.x;
            As[nb][aK+1][aRow] = a4n.y;
            As[nb][aK+2][aRow] = a4n.z;
            As[nb][aK+3][aRow] = a4n.w;
            *reinterpret_cast<float4*>(&Bs[nb][bRow][bCol]) = b4n;
            __syncthreads();
            buf = nb;
        }
    }
}

// Standard epilogue: C = acc (+bias) (+C residual)
__device__ __forceinline__ void sgemm_epilogue(
    float* __restrict__ C, const float* __restrict__ bias,
    int N, int residual, int bm, int bn, float acc[8][8])
{
    int tid = threadIdx.x;
    int mr = (tid >> 4) * 8;
    int nc = (tid & 15) * 8;

    float bvals[8];
    #pragma unroll
    for (int j = 0; j < 8; j++) bvals[j] = bias ? bias[bn + nc + j] : 0.f;

    #pragma unroll
    for (int i = 0; i < 8; i++) {
        size_t crow = (size_t)(bm + mr + i) * N + bn + nc;
        float4 r0, r1;
        if (residual) {
            float4 c0 = *reinterpret_cast<const float4*>(&C[crow]);
            float4 c1 = *reinterpret_cast<const float4*>(&C[crow+4]);
            r0.x = acc[i][0]+bvals[0]+c0.x; r0.y = acc[i][1]+bvals[1]+c0.y;
            r0.z = acc[i][2]+bvals[2]+c0.z; r0.w = acc[i][3]+bvals[3]+c0.w;
            r1.x = acc[i][4]+bvals[4]+c1.x; r1.y = acc[i][5]+bvals[5]+c1.y;
            r1.z = acc[i][6]+bvals[6]+c1.z; r1.w = acc[i][7]+bvals[7]+c1.w;
        } else {
            r0.x = acc[i][0]+bvals[0]; r0.y = acc[i][1]+bvals[1];
            r0.z = acc[i][2]+bvals[2]; r0.w = acc[i][3]+bvals[3];
            r1.x = acc[i][4]+bvals[4]; r1.y = acc[i][5]+bvals[5];
            r1.z = acc[i][6]+bvals[6]; r1.w = acc[i][7]+bvals[7];
        }
        *reinterpret_cast<float4*>(&C[crow])   = r0;
        *reinterpret_cast<float4*>(&C[crow+4]) = r1;
    }
}

// Generic single-GEMM entry
__global__ void __launch_bounds__(256) sgemm_kernel(
    const float* __restrict__ A, const float* __restrict__ B,
    float* __restrict__ C, const float* __restrict__ bias,
    int M, int N, int K, int residual)
{
    __shared__ float As[2][8][128];
    __shared__ float Bs[2][8][128];
    float acc[8][8];
    sgemm_core(A, B, N, K, blockIdx.y * 128, blockIdx.x * 128, As, Bs, acc);
    sgemm_epilogue(C, bias, N, residual, blockIdx.y * 128, blockIdx.x * 128, acc);
}

// Fused Q/K/V projection: one launch, grid.z in {0,1,2} selects weight/output.
__global__ void __launch_bounds__(256) qkv_gemm_kernel(
    const float* __restrict__ A,
    const float* __restrict__ Bq, const float* __restrict__ Bk,
    const float* __restrict__ Bv,
    float* __restrict__ Cq, float* __restrict__ Ck, float* __restrict__ Cv)
{
    __shared__ float As[2][8][128];
    __shared__ float Bs[2][8][128];
    const float* B = (blockIdx.z == 0) ? Bq : (blockIdx.z == 1) ? Bk : Bv;
    float*       C = (blockIdx.z == 0) ? Cq : (blockIdx.z == 1) ? Ck : Cv;
    float acc[8][8];
    sgemm_core(A, B, DIMC, DIMC, blockIdx.y * 128, blockIdx.x * 128, As, Bs, acc);
    sgemm_epilogue(C, nullptr, DIMC, 0, blockIdx.y * 128, blockIdx.x * 128, acc);
}

// ---------------------------------------------------------------------------
// Fused FF-in: act[:, bn:bn+128] = (tn@Win_a + b_a) * gelu(tn@Win_g + b_g)
// where Win_a = Win[:, bn:bn+128], Win_g = Win[:, DFF+bn:DFF+bn+128].
// Two K-loops per block (g-panel first, gelu stashed per-thread in padded
// smem; then a-panel, multiply in epilogue). Math identical to the previous
// sgemm(h) + gelumul(act) pair; the h buffer round-trip is eliminated.
// ---------------------------------------------------------------------------
__global__ void __launch_bounds__(256, 2) ffin_gemm_kernel(
    const float* __restrict__ A, const float* __restrict__ B,
    const float* __restrict__ bias, float* __restrict__ act)
{
    extern __shared__ float dyn[];
    float (*As)[8][128] = reinterpret_cast<float(*)[8][128]>(dyn);
    float (*Bs)[8][128] = reinterpret_cast<float(*)[8][128]>(dyn + 2*8*128);
    float* Gmy = dyn + 4*8*128 + threadIdx.x * 65;   // 64 used, pad to 65

    int bm = blockIdx.y * 128;
    int bnA = blockIdx.x * 128;          // a-panel column base in [0, DFF)
    int bnG = DFFC + bnA;                // g-panel column base
    int nc = (threadIdx.x & 15) * 8;

    float acc[8][8];

    // ---- pass G: g = tn@Win_g + b_g; stash gelu(g) ----
    sgemm_core(A, B, 2*DFFC, DIMC, bm, bnG, As, Bs, acc);
    #pragma unroll
    for (int j = 0; j < 8; j++) {
        float bg = bias[bnG + nc + j];
        #pragma unroll
        for (int i = 0; i < 8; i++) {
            float g = acc[i][j] + bg;
            Gmy[i*8 + j] = 0.5f * g * (1.f + erff(g * 0.70710678118654752f));
        }
    }
    __syncthreads();   // all As/Bs reads of pass G done before pass A preload

    // ---- pass A: a = tn@Win_a + b_a; act = a * gelu_g ----
    sgemm_core(A, B, 2*DFFC, DIMC, bm, bnA, As, Bs, acc);

    int mr = (threadIdx.x >> 4) * 8;
    float bvals[8];
    #pragma unroll
    for (int j = 0; j < 8; j++) bvals[j] = bias[bnA + nc + j];

    #pragma unroll
    for (int i = 0; i < 8; i++) {
        size_t crow = (size_t)(bm + mr + i) * DFFC + bnA + nc;
        float4 r0, r1;
        r0.x = (acc[i][0]+bvals[0]) * Gmy[i*8+0];
        r0.y = (acc[i][1]+bvals[1]) * Gmy[i*8+1];
        r0.z = (acc[i][2]+bvals[2]) * Gmy[i*8+2];
        r0.w = (acc[i][3]+bvals[3]) * Gmy[i*8+3];
        r1.x = (acc[i][4]+bvals[4]) * Gmy[i*8+4];
        r1.y = (acc[i][5]+bvals[5]) * Gmy[i*8+5];
        r1.z = (acc[i][6]+bvals[6]) * Gmy[i*8+6];
        r1.w = (acc[i][7]+bvals[7]) * Gmy[i*8+7];
        *reinterpret_cast<float4*>(&act[crow])   = r0;
        *reinterpret_cast<float4*>(&act[crow+4]) = r1;
    }
}

// ---------------------------------------------------------------------------
// mix = sigmoid(tn@Wmix + bmix), gate = sigmoid(tn@Wg). One block per token.
// ---------------------------------------------------------------------------
__global__ void mixgate_kernel(const float* __restrict__ tn,
                               const float* __restrict__ Wmix,
                               const float* __restrict__ bmix,
                               const float* __restrict__ Wg,
                               float* __restrict__ mix,
                               float* __restrict__ gate)
{
    __shared__ float row[DIMC];
    int tok = blockIdx.x;
    const float* tr = tn + (size_t)tok * DIMC;
    for (int i = threadIdx.x; i < DIMC; i += 256) row[i] = tr[i];
    __syncthreads();

    int lane = threadIdx.x & 31, w = threadIdx.x >> 5;
    #pragma unroll
    for (int r = 0; r < 3; r++) {
        int ocol = w + r * 8;                 // 0..23
        int h = (ocol < HEADSC) ? ocol : ocol - HEADSC;
        const float* W = (ocol < HEADSC) ? Wmix : Wg;
        float s = 0.f;
        for (int d = lane; d < DIMC; d += 32) s += row[d] * W[d*HEADSC + h];
        #pragma unroll
        for (int off = 16; off; off >>= 1) s += __shfl_down_sync(0xffffffffu, s, off);
        if (lane == 0) {
            if (ocol < HEADSC) mix[(size_t)tok*HEADSC + h] = 1.f/(1.f + __expf(-(s + bmix[h])));
            else               gate[(size_t)tok*HEADSC + h] = 1.f/(1.f + __expf(-s));
        }
    }
}

// ---------------------------------------------------------------------------
// Fused q/k/v post-processing. One warp per (token, head):
//   k <- l2norm(k)*(kgam+1)*sqrt(DH), then rope(k) on time layers
//   q <- rope(q) on time layers
//   v <- v + mix*(rv - v)
// ---------------------------------------------------------------------------
__global__ void qkv_post_kernel(float* __restrict__ q, float* __restrict__ k,
                                float* __restrict__ v,
                                const float* __restrict__ rv,
                                const float* __restrict__ mix,
                                const float* __restrict__ kgam,
                                int timeL)
{
    int gw = blockIdx.x * 8 + (threadIdx.x >> 5);   // warp id = token*HEADS+head
    int lane = threadIdx.x & 31;
    int tok = gw / HEADSC, h = gw % HEADSC;
    size_t base = (size_t)tok*DIMC + h*DHC;

    // --- knorm ---
    float* kp = k + base;
    float a = kp[lane], b = kp[lane+32];
    float ss = a*a + b*b;
    #pragma unroll
    for (int off = 16; off; off >>= 1) ss += __shfl_xor_sync(0xffffffffu, ss, off);
    float inv = 1.f / fmaxf(sqrtf(ss), 1e-12f);
    float k1 = a * inv * (kgam[h*DHC + lane]      + 1.f) * 8.0f;
    float k2 = b * inv * (kgam[h*DHC + lane + 32] + 1.f) * 8.0f;

    if (timeL) {
        int t = (tok / SC) % TC;
        float invf = expf(-(float)lane * (9.210340371976184f / 32.f)); // 10000^(-i/32)
        float th = (float)t * invf;
        float c = cosf(th), sn = sinf(th);
        kp[lane]      = k1*c - k2*sn;
        kp[lane + 32] = k2*c + k1*sn;
        float* qp = q + base;
        float q1 = qp[lane], q2 = qp[lane+32];
        qp[lane]      = q1*c - q2*sn;
        qp[lane + 32] = q2*c + q1*sn;
    } else {
        kp[lane]      = k1;
        kp[lane + 32] = k2;
    }

    // --- v value-residual lerp ---
    float m = mix[(size_t)tok*HEADSC + h];
    float* vp = v + base;
    const float* rp = rv + base;
    float v1 = vp[lane], v2 = vp[lane+32];
    vp[lane]      = v1 + m * (rp[lane]      - v1);
    vp[lane + 32] = v2 + m * (rp[lane + 32] - v2);
}

// ---------------------------------------------------------------------------
// Space attention: non-causal, seq along S (len 256).
// One block per (b*T+t, head); 256 threads = one query each.
// SINGLE-PASS softmax: scores softclamped to (-50, 50], m = 50 analytic bound.
// K,V staged in 128KB dynamic smem.
// ---------------------------------------------------------------------------
__global__ void __launch_bounds__(256) attn_space_kernel(
    const float* __restrict__ q, const float* __restrict__ k,
    const float* __restrict__ v, const float* __restrict__ gate,
    float* __restrict__ o)
{
    extern __shared__ float sm[];
    float* Ks = sm;
    float* Vs = sm + SC*DHC;
    int seq = blockIdx.x;            // b*T + t
    int h = blockIdx.y;
    int base = seq * SC;             // token base, stride 1 over s
    int tid = threadIdx.x;

    for (int idx = tid; idx < SC*DHC; idx += 256) {
        int row = idx >> 6, d = idx & 63;
        size_t g = (size_t)(base + row)*DIMC + h*DHC + d;
        Ks[idx] = k[g];
        Vs[idx] = v[g];
    }
    __syncthreads();

    size_t qoff = (size_t)(base + tid)*DIMC + h*DHC;
    float4 qr[16];
    const float4* qp = reinterpret_cast<const float4*>(q + qoff);
    #pragma unroll
    for (int i = 0; i < 16; i++) qr[i] = qp[i];

    float acc[DHC];
    #pragma unroll
    for (int d = 0; d < DHC; d++) acc[d] = 0.f;
    float l = 0.f;
    for (int j = 0; j < SC; j++) {
        const float4* kj = reinterpret_cast<const float4*>(Ks + j*DHC);
        float s = 0.f;
        #pragma unroll
        for (int i = 0; i < 16; i++) {
            float4 kk = kj[i];
            s = fmaf(qr[i].x, kk.x, s); s = fmaf(qr[i].y, kk.y, s);
            s = fmaf(qr[i].z, kk.z, s); s = fmaf(qr[i].w, kk.w, s);
        }
        s = 50.f * __tanhf(s * (0.125f * 0.02f));
        float p = __expf(s - 50.f);
        l += p;
        const float4* vj = reinterpret_cast<const float4*>(Vs + j*DHC);
        #pragma unroll
        for (int i = 0; i < 16; i++) {
            float4 vv = vj[i];
            acc[i*4+0] = fmaf(p, vv.x, acc[i*4+0]);
            acc[i*4+1] = fmaf(p, vv.y, acc[i*4+1]);
            acc[i*4+2] = fmaf(p, vv.z, acc[i*4+2]);
            acc[i*4+3] = fmaf(p, vv.w, acc[i*4+3]);
        }
    }
    float gs = gate[(size_t)(base + tid)*HEADSC + h] / l;
    float* op = o + qoff;
    #pragma unroll
    for (int d = 0; d < DHC; d++) op[d] = acc[d] * gs;
}

// ---------------------------------------------------------------------------
// Time attention: causal, seq along T (len 32). One warp per (b*S+s, head).
// Single-pass softmax with analytic max 50.
// ---------------------------------------------------------------------------
__global__ void attn_time_kernel(
    const float* __restrict__ q, const float* __restrict__ k,
    const float* __restrict__ v, const float* __restrict__ gate,
    float* __restrict__ o)
{
    __shared__ float Ks[TC*DHC];
    __shared__ float Vs[TC*DHC];
    int bs = blockIdx.x;             // b*S + s
    int h = blockIdx.y;
    int b = bs / SC, s = bs % SC;
    int tokBase = b*TC*SC + s;       // token(t) = tokBase + t*S
    int lane = threadIdx.x;

    for (int idx = lane; idx < TC*DHC; idx += 32) {
        int row = idx >> 6, d = idx & 63;
        size_t g = (size_t)(tokBase + row*SC)*DIMC + h*DHC + d;
        Ks[idx] = k[g];
        Vs[idx] = v[g];
    }
    __syncwarp();

    int tok = tokBase + lane*SC;     // query at t = lane
    size_t qoff = (size_t)tok*DIMC + h*DHC;
    float4 qr[16];
    const float4* qp = reinterpret_cast<const float4*>(q + qoff);
    #pragma unroll
    for (int i = 0; i < 16; i++) qr[i] = qp[i];

    float acc[DHC];
    #pragma unroll
    for (int d = 0; d < DHC; d++) acc[d] = 0.f;
    float l = 0.f;
    for (int j = 0; j <= lane; j++) {
        const float4* kj = reinterpret_cast<const float4*>(Ks + j*DHC);
        float sc = 0.f;
        #pragma unroll
        for (int i = 0; i < 16; i++) {
            float4 kk = kj[i];
            sc = fmaf(qr[i].x, kk.x, sc); sc = fmaf(qr[i].y, kk.y, sc);
            sc = fmaf(qr[i].z, kk.z, sc); sc = fmaf(qr[i].w, kk.w, sc);
        }
        sc = 50.f * __tanhf(sc * (0.125f * 0.02f));
        float p = __expf(sc - 50.f);
        l += p;
        const float4* vj = reinterpret_cast<const float4*>(Vs + j*DHC);
        #pragma unroll
        for (int i = 0; i < 16; i++) {
            float4 vv = vj[i];
            acc[i*4+0] = fmaf(p, vv.x, acc[i*4+0]);
            acc[i*4+1] = fmaf(p, vv.y, acc[i*4+1]);
            acc[i*4+2] = fmaf(p, vv.z, acc[i*4+2]);
            acc[i*4+3] = fmaf(p, vv.w, acc[i*4+3]);
        }
    }
    float gs = gate[(size_t)tok*HEADSC + h] / l;
    float* op = o + qoff;
    #pragma unroll
    for (int d = 0; d < DHC; d++) op[d] = acc[d] * gs;
}

// ---------------------------------------------------------------------------
// Orchestration
// ---------------------------------------------------------------------------
extern "C" void kernel_launch(void* const* d_in, const int* in_sizes, int n_in,
                              void* d_out, int out_size)
{
    (void)in_sizes; (void)n_in; (void)out_size;
    const float* tokens      = (const float*)d_in[0];
    const float* attn_norm_w = (const float*)d_in[1];
    const float* Wq          = (const float*)d_in[2];
    const float* Wk          = (const float*)d_in[3];
    const float* Wv          = (const float*)d_in[4];
    const float* Wo          = (const float*)d_in[5];
    const float* Wg          = (const float*)d_in[6];
    const float* Wmix        = (const float*)d_in[7];
    const float* bmix        = (const float*)d_in[8];
    const float* kgam        = (const float*)d_in[9];
    const float* ffnw        = (const float*)d_in[10];
    const float* Win         = (const float*)d_in[11];
    const float* b_in        = (const float*)d_in[12];
    const float* Wout        = (const float*)d_in[13];
    const float* b_out       = (const float*)d_in[14];
    const float* vrnw        = (const float*)d_in[15];
    const float* vrW         = (const float*)d_in[16];
    const float* fnw         = (const float*)d_in[17];
    float* out = (float*)d_out;

    float *x,*tn,*q,*k,*v,*o,*rv,*mix,*gate,*act;
    cudaGetSymbolAddress((void**)&x,   g_x);
    cudaGetSymbolAddress((void**)&tn,  g_tn);
    cudaGetSymbolAddress((void**)&q,   g_q);
    cudaGetSymbolAddress((void**)&k,   g_k);
    cudaGetSymbolAddress((void**)&v,   g_v);
    cudaGetSymbolAddress((void**)&o,   g_o);
    cudaGetSymbolAddress((void**)&rv,  g_rv);
    cudaGetSymbolAddress((void**)&mix, g_mix);
    cudaGetSymbolAddress((void**)&gate,g_gate);
    cudaGetSymbolAddress((void**)&act, g_act);

    cudaFuncSetAttribute(attn_space_kernel,
                         cudaFuncAttributeMaxDynamicSharedMemorySize, SMEM_SP);
    cudaFuncSetAttribute(ffin_gemm_kernel,
                         cudaFuncAttributeMaxDynamicSharedMemorySize, FF_SMEM);

    // x = tokens
    cudaMemcpyAsync(x, tokens, sizeof(float)*(size_t)NTOK*DIMC,
                    cudaMemcpyDeviceToDevice, 0);

    dim3 g768(DIMC/128, NTOK/128);       // N=768 GEMMs
    dim3 gqkv(DIMC/128, NTOK/128, 3);    // fused QKV
    dim3 gffin(DFFC/128, NTOK/128);      // fused FF-in (a,g panels per block)

    // value residuals from original tokens
    rmsnorm_kernel<<<NTOK, 256>>>(tokens, vrnw, tn);
    sgemm_kernel<<<g768, 256>>>(tn, vrW, rv, nullptr, NTOK, DIMC, DIMC, 0);

    for (int i = 0; i < DEPTHC; i++) {
        // ---- attention sublayer ----
        rmsnorm_kernel<<<NTOK, 256>>>(x, attn_norm_w + (size_t)i*DIMC, tn);
        qkv_gemm_kernel<<<gqkv, 256>>>(tn,
                                       Wq + (size_t)i*DIMC*DIMC,
                                       Wk + (size_t)i*DIMC*DIMC,
                                       Wv + (size_t)i*DIMC*DIMC,
                                       q, k, v);
        mixgate_kernel<<<NTOK, 256>>>(tn, Wmix + (size_t)i*DIMC*HEADSC,
                                      bmix + (size_t)i*HEADSC,
                                      Wg + (size_t)i*DIMC*HEADSC, mix, gate);

        bool timeL = (((i + 1) % 4) == 0);
        qkv_post_kernel<<<(NTOK*HEADSC)/8, 256>>>(q, k, v, rv, mix,
                                                  kgam + (size_t)i*HEADSC*DHC,
                                                  timeL ? 1 : 0);
        if (timeL) {
            attn_time_kernel<<<dim3(BC*SC, HEADSC), 32>>>(q, k, v, gate, o);
        } else {
            attn_space_kernel<<<dim3(BC*TC, HEADSC), 256, SMEM_SP>>>(q, k, v, gate, o);
        }
        // x += o @ Wo
        sgemm_kernel<<<g768, 256>>>(o, Wo + (size_t)i*DIMC*DIMC, x, nullptr, NTOK, DIMC, DIMC, 1);

        // ---- feedforward sublayer ----
        rmsnorm_kernel<<<NTOK, 256>>>(x, ffnw + (size_t)i*DIMC, tn);
        ffin_gemm_kernel<<<gffin, 256, FF_SMEM>>>(tn, Win + (size_t)i*DIMC*2*DFFC,
                                                  b_in + (size_t)i*2*DFFC, act);
        // x += act @ Wout + b_out
        sgemm_kernel<<<g768, 256>>>(act, Wout + (size_t)i*DFFC*DIMC, x,
                                    b_out + (size_t)i*DIMC, NTOK, DIMC, DFFC, 1);
    }

    rmsnorm_kernel<<<NTOK, 256>>>(x, fnw, out);
}

// round 13
// speedup vs baseline: 2.0004x; 2.0004x over previous
#include <cuda_runtime.h>
#include <cuda_fp16.h>
#include <math.h>
#include <stdint.h>

// ---------------------------------------------------------------------------
// Problem constants
// ---------------------------------------------------------------------------
#define DIMC   768
#define DEPTHC 8
#define HEADSC 12
#define DHC    64
#define DFFC   2048
#define BC     2
#define TC     32
#define SC     256
#define NTOK   (BC*TC*SC)          // 16384 tokens
#define SMEM_SP (2*SC*DHC*(int)sizeof(float))  // 128 KB for space attention K+V

// hgemm smem: per stage Ahi|Alo (128x24 halves each) + Bhi|Blo (16x136 each)
#define A_SZ (128*24)
#define B_SZ (16*136)
#define HSTAGE (2*A_SZ + 2*B_SZ)     // 10496 halves
#define HSMEM  (2*HSTAGE*(int)sizeof(__half))   // 41984 B < 48K default

// ---------------------------------------------------------------------------
// Static device scratch
// ---------------------------------------------------------------------------
__device__ float g_x  [NTOK*DIMC];
__device__ float g_q  [NTOK*DIMC];
__device__ float g_k  [NTOK*DIMC];
__device__ float g_v  [NTOK*DIMC];
__device__ float g_rv [NTOK*DIMC];
__device__ float g_h  [NTOK*2*DFFC];
__device__ float g_mix [NTOK*HEADSC];
__device__ float g_gate[NTOK*HEADSC];

__device__ __half g_tnh[NTOK*DIMC],  g_tnl[NTOK*DIMC];
__device__ __half g_oh [NTOK*DIMC],  g_ol [NTOK*DIMC];
__device__ __half g_acth[NTOK*DFFC], g_actl[NTOK*DFFC];

// pre-decomposed weights (all layers)
__device__ __half g_Wqh[DEPTHC*DIMC*DIMC],  g_Wql[DEPTHC*DIMC*DIMC];
__device__ __half g_Wkh[DEPTHC*DIMC*DIMC],  g_Wkl[DEPTHC*DIMC*DIMC];
__device__ __half g_Wvh[DEPTHC*DIMC*DIMC],  g_Wvl[DEPTHC*DIMC*DIMC];
__device__ __half g_Woh2[DEPTHC*DIMC*DIMC], g_Wol2[DEPTHC*DIMC*DIMC];
__device__ __half g_Winh[DEPTHC*DIMC*2*DFFC], g_Winl[DEPTHC*DIMC*2*DFFC];
__device__ __half g_Wouth[DEPTHC*DFFC*DIMC],  g_Woutl[DEPTHC*DFFC*DIMC];
__device__ __half g_vrWh[DIMC*DIMC], g_vrWl[DIMC*DIMC];

// ---------------------------------------------------------------------------
// helpers
// ---------------------------------------------------------------------------
__device__ __forceinline__ void split2(float x, __half& h, __half& l)
{
    h = __float2half_rn(x);
    l = __float2half_rn(x - __half2float(h));
}

#define LDSM_X4(r, addr) \
    asm volatile("ldmatrix.sync.aligned.m8n8.x4.shared.b16 {%0,%1,%2,%3}, [%4];" \
        : "=r"((r)[0]), "=r"((r)[1]), "=r"((r)[2]), "=r"((r)[3]) : "r"(addr))

#define LDSM_X2_T(r, addr) \
    asm volatile("ldmatrix.sync.aligned.m8n8.x2.trans.shared.b16 {%0,%1}, [%2];" \
        : "=r"((r)[0]), "=r"((r)[1]) : "r"(addr))

#define MMA16816(d, a, b) \
    asm volatile("mma.sync.aligned.m16n8k16.row.col.f32.f16.f16.f32 " \
        "{%0,%1,%2,%3}, {%4,%5,%6,%7}, {%8,%9}, {%0,%1,%2,%3};" \
        : "+f"((d)[0]), "+f"((d)[1]), "+f"((d)[2]), "+f"((d)[3]) \
        : "r"((a)[0]), "r"((a)[1]), "r"((a)[2]), "r"((a)[3]), \
          "r"((b)[0]), "r"((b)[1]))

// ---------------------------------------------------------------------------
// decompose: fp32 -> (fp16 hi, fp16 lo), grid-stride
// ---------------------------------------------------------------------------
__global__ void decomp_kernel(const float* __restrict__ src,
                              __half* __restrict__ hi, __half* __restrict__ lo,
                              int n)
{
    for (int i = blockIdx.x * blockDim.x + threadIdx.x; i < n;
         i += gridDim.x * blockDim.x) {
        __half h, l;
        split2(src[i], h, l);
        hi[i] = h; lo[i] = l;
    }
}

// ---------------------------------------------------------------------------
// RMSNorm fp32 out (final layer only)
// ---------------------------------------------------------------------------
__global__ void rmsnorm_kernel(const float* __restrict__ x,
                               const float* __restrict__ w,
                               float* __restrict__ out)
{
    int tok = blockIdx.x;
    const float* xp = x + (size_t)tok * DIMC;
    int t = threadIdx.x;
    float v0 = xp[t], v1 = xp[t+256], v2 = xp[t+512];
    float ss = v0*v0 + v1*v1 + v2*v2;

    __shared__ float sh[8];
    int lane = t & 31, wid = t >> 5;
    #pragma unroll
    for (int off = 16; off; off >>= 1) ss += __shfl_down_sync(0xffffffffu, ss, off);
    if (lane == 0) sh[wid] = ss;
    __syncthreads();
    if (wid == 0) {
        float v = (lane < 8) ? sh[lane] : 0.f;
        #pragma unroll
        for (int off = 16; off; off >>= 1) v += __shfl_down_sync(0xffffffffu, v, off);
        if (lane == 0) sh[0] = v;
    }
    __syncthreads();
    float scale = rsqrtf(sh[0] * (1.0f/DIMC) + 1e-6f);
    float* op = out + (size_t)tok * DIMC;
    op[t]     = v0 * scale * w[t];
    op[t+256] = v1 * scale * w[t+256];
    op[t+512] = v2 * scale * w[t+512];
}

// RMSNorm with hi/lo fp16 output (feeds hgemm A-side)
__global__ void rmsnorm_hl_kernel(const float* __restrict__ x,
                                  const float* __restrict__ w,
                                  __half* __restrict__ oh,
                                  __half* __restrict__ ol)
{
    int tok = blockIdx.x;
    const float* xp = x + (size_t)tok * DIMC;
    int t = threadIdx.x;
    float v0 = xp[t], v1 = xp[t+256], v2 = xp[t+512];
    float ss = v0*v0 + v1*v1 + v2*v2;

    __shared__ float sh[8];
    int lane = t & 31, wid = t >> 5;
    #pragma unroll
    for (int off = 16; off; off >>= 1) ss += __shfl_down_sync(0xffffffffu, ss, off);
    if (lane == 0) sh[wid] = ss;
    __syncthreads();
    if (wid == 0) {
        float v = (lane < 8) ? sh[lane] : 0.f;
        #pragma unroll
        for (int off = 16; off; off >>= 1) v += __shfl_down_sync(0xffffffffu, v, off);
        if (lane == 0) sh[0] = v;
    }
    __syncthreads();
    float scale = rsqrtf(sh[0] * (1.0f/DIMC) + 1e-6f);
    size_t b = (size_t)tok * DIMC;
    __half h, l;
    split2(v0 * scale * w[t],     h, l); oh[b+t]     = h; ol[b+t]     = l;
    split2(v1 * scale * w[t+256], h, l); oh[b+t+256] = h; ol[b+t+256] = l;
    split2(v2 * scale * w[t+512], h, l); oh[b+t+512] = h; ol[b+t+512] = l;
}

// ---------------------------------------------------------------------------
// hgemm core: C[M,N] = (Ahi+Alo)@(Bhi+Blo) via 3-term fp16 mma, f32 accum.
// A [M,K] row-major fp16 pair; B [K,N] row-major fp16 pair.
// Block 128x128, 8 warps (2x4), warp tile 64x32, K-step 16.
// ---------------------------------------------------------------------------
__device__ __forceinline__ void hgemm_core(
    const __half* __restrict__ Ahi, const __half* __restrict__ Alo,
    const __half* __restrict__ Bhi, const __half* __restrict__ Blo,
    float* __restrict__ C, const float* __restrict__ bias,
    int N, int K, int residual, int bm, int bn, __half* hs)
{
    int t = threadIdx.x;
    // global load mapping
    int ar = t >> 1,  ac = (t & 1) * 8;      // A: row, k-chunk
    int br = t >> 4,  bc = (t & 15) * 8;     // B: k-row, n-chunk
    const __half* gAh = &Ahi[(size_t)(bm + ar) * K + ac];
    const __half* gAl = &Alo[(size_t)(bm + ar) * K + ac];
    const __half* gBh = &Bhi[(size_t)br * N + bn + bc];
    const __half* gBl = &Blo[(size_t)br * N + bn + bc];
    int sAoff = ar * 24 + ac;
    int sBoff = br * 136 + bc;

    // preload stage 0
    *(int4*)&hs[0*HSTAGE + sAoff]               = *(const int4*)&gAh[0];
    *(int4*)&hs[0*HSTAGE + A_SZ + sAoff]        = *(const int4*)&gAl[0];
    *(int4*)&hs[0*HSTAGE + 2*A_SZ + sBoff]      = *(const int4*)&gBh[0];
    *(int4*)&hs[0*HSTAGE + 2*A_SZ + B_SZ + sBoff] = *(const int4*)&gBl[0];
    __syncthreads();

    int wid = t >> 5, lane = t & 31;
    int wm = wid >> 2, wn = wid & 3;
    // ldmatrix element offsets (within a stage)
    int aOff = (wm*64 + ((lane >> 3) & 1)*8 + (lane & 7)) * 24 + ((lane >> 4) & 1)*8;
    int bOff = (lane & 15) * 136 + wn * 32;

    float acc[4][4][4];
    #pragma unroll
    for (int mt = 0; mt < 4; mt++)
        #pragma unroll
        for (int nt = 0; nt < 4; nt++)
            #pragma unroll
            for (int r = 0; r < 4; r++) acc[mt][nt][r] = 0.f;

    int buf = 0;
    for (int k0 = 0; k0 < K; k0 += 16) {
        bool nxt = (k0 + 16) < K;
        int4 rAh, rAl, rBh, rBl;
        if (nxt) {
            rAh = *(const int4*)&gAh[k0 + 16];
            rAl = *(const int4*)&gAl[k0 + 16];
            rBh = *(const int4*)&gBh[(size_t)(k0 + 16) * N];
            rBl = *(const int4*)&gBl[(size_t)(k0 + 16) * N];
        }

        uint32_t base  = (uint32_t)__cvta_generic_to_shared(&hs[buf*HSTAGE]);
        uint32_t aHb = base;
        uint32_t aLb = base + A_SZ*2;
        uint32_t bHb = base + 2*A_SZ*2;
        uint32_t bLb = bHb + B_SZ*2;

        uint32_t bh[4][2], bl[4][2];
        #pragma unroll
        for (int nt = 0; nt < 4; nt++) {
            LDSM_X2_T(bh[nt], bHb + (uint32_t)(bOff + nt*8)*2);
            LDSM_X2_T(bl[nt], bLb + (uint32_t)(bOff + nt*8)*2);
        }
        #pragma unroll
        for (int mt = 0; mt < 4; mt++) {
            uint32_t ah[4], al[4];
            LDSM_X4(ah, aHb + (uint32_t)(aOff + mt*16*24)*2);
            LDSM_X4(al, aLb + (uint32_t)(aOff + mt*16*24)*2);
            #pragma unroll
            for (int nt = 0; nt < 4; nt++) {
                MMA16816(acc[mt][nt], ah, bh[nt]);
                MMA16816(acc[mt][nt], ah, bl[nt]);
                MMA16816(acc[mt][nt], al, bh[nt]);
            }
        }

        if (nxt) {
            int nb = buf ^ 1;
            *(int4*)&hs[nb*HSTAGE + sAoff]                = rAh;
            *(int4*)&hs[nb*HSTAGE + A_SZ + sAoff]         = rAl;
            *(int4*)&hs[nb*HSTAGE + 2*A_SZ + sBoff]       = rBh;
            *(int4*)&hs[nb*HSTAGE + 2*A_SZ + B_SZ + sBoff] = rBl;
            __syncthreads();
            buf = nb;
        }
    }

    // epilogue
    int gid = lane >> 2, qid = lane & 3;
    #pragma unroll
    for (int mt = 0; mt < 4; mt++) {
        #pragma unroll
        for (int nt = 0; nt < 4; nt++) {
            int row = bm + wm*64 + mt*16 + gid;
            int col = bn + wn*32 + nt*8 + qid*2;
            float bb0 = 0.f, bb1 = 0.f;
            if (bias) { bb0 = bias[col]; bb1 = bias[col+1]; }
            float* p0 = &C[(size_t)row * N + col];
            float* p1 = &C[(size_t)(row + 8) * N + col];
            float2 r0, r1;
            r0.x = acc[mt][nt][0] + bb0; r0.y = acc[mt][nt][1] + bb1;
            r1.x = acc[mt][nt][2] + bb0; r1.y = acc[mt][nt][3] + bb1;
            if (residual) {
                float2 o0 = *(float2*)p0, o1 = *(float2*)p1;
                r0.x += o0.x; r0.y += o0.y; r1.x += o1.x; r1.y += o1.y;
            }
            *(float2*)p0 = r0;
            *(float2*)p1 = r1;
        }
    }
}

__global__ void __launch_bounds__(256, 2) hgemm_kernel(
    const __half* __restrict__ Ahi, const __half* __restrict__ Alo,
    const __half* __restrict__ Bhi, const __half* __restrict__ Blo,
    float* __restrict__ C, const float* __restrict__ bias,
    int N, int K, int residual)
{
    extern __shared__ __half hs[];
    hgemm_core(Ahi, Alo, Bhi, Blo, C, bias, N, K, residual,
               blockIdx.y * 128, blockIdx.x * 128, hs);
}

// fused QKV: grid.z selects (Wq->q, Wk->k, Wv->v); A shared
__global__ void __launch_bounds__(256, 2) hgemm_qkv_kernel(
    const __half* __restrict__ Ahi, const __half* __restrict__ Alo,
    const __half* __restrict__ Bqh, const __half* __restrict__ Bql,
    const __half* __restrict__ Bkh, const __half* __restrict__ Bkl,
    const __half* __restrict__ Bvh, const __half* __restrict__ Bvl,
    float* __restrict__ Cq, float* __restrict__ Ck, float* __restrict__ Cv)
{
    extern __shared__ __half hs[];
    const __half* Bh = (blockIdx.z == 0) ? Bqh : (blockIdx.z == 1) ? Bkh : Bvh;
    const __half* Bl = (blockIdx.z == 0) ? Bql : (blockIdx.z == 1) ? Bkl : Bvl;
    float*        C  = (blockIdx.z == 0) ? Cq  : (blockIdx.z == 1) ? Ck  : Cv;
    hgemm_core(Ahi, Alo, Bh, Bl, C, nullptr, DIMC, DIMC, 0,
               blockIdx.y * 128, blockIdx.x * 128, hs);
}

// ---------------------------------------------------------------------------
// mix = sigmoid(tn@Wmix + bmix), gate = sigmoid(tn@Wg). tn from hi+lo.
// ---------------------------------------------------------------------------
__global__ void mixgate_kernel(const __half* __restrict__ tnh,
                               const __half* __restrict__ tnl,
                               const float* __restrict__ Wmix,
                               const float* __restrict__ bmix,
                               const float* __restrict__ Wg,
                               float* __restrict__ mix,
                               float* __restrict__ gate)
{
    __shared__ float row[DIMC];
    int tok = blockIdx.x;
    size_t b = (size_t)tok * DIMC;
    for (int i = threadIdx.x; i < DIMC; i += 256)
        row[i] = __half2float(tnh[b+i]) + __half2float(tnl[b+i]);
    __syncthreads();

    int lane = threadIdx.x & 31, w = threadIdx.x >> 5;
    #pragma unroll
    for (int r = 0; r < 3; r++) {
        int ocol = w + r * 8;                 // 0..23
        int h = (ocol < HEADSC) ? ocol : ocol - HEADSC;
        const float* W = (ocol < HEADSC) ? Wmix : Wg;
        float s = 0.f;
        for (int d = lane; d < DIMC; d += 32) s += row[d] * W[d*HEADSC + h];
        #pragma unroll
        for (int off = 16; off; off >>= 1) s += __shfl_down_sync(0xffffffffu, s, off);
        if (lane == 0) {
            if (ocol < HEADSC) mix[(size_t)tok*HEADSC + h] = 1.f/(1.f + __expf(-(s + bmix[h])));
            else               gate[(size_t)tok*HEADSC + h] = 1.f/(1.f + __expf(-s));
        }
    }
}

// ---------------------------------------------------------------------------
// Fused q/k/v post-processing (fp32 in place). One warp per (token, head).
// ---------------------------------------------------------------------------
__global__ void qkv_post_kernel(float* __restrict__ q, float* __restrict__ k,
                                float* __restrict__ v,
                                const float* __restrict__ rv,
                                const float* __restrict__ mix,
                                const float* __restrict__ kgam,
                                int timeL)
{
    int gw = blockIdx.x * 8 + (threadIdx.x >> 5);
    int lane = threadIdx.x & 31;
    int tok = gw / HEADSC, h = gw % HEADSC;
    size_t base = (size_t)tok*DIMC + h*DHC;

    float* kp = k + base;
    float a = kp[lane], b = kp[lane+32];
    float ss = a*a + b*b;
    #pragma unroll
    for (int off = 16; off; off >>= 1) ss += __shfl_xor_sync(0xffffffffu, ss, off);
    float inv = 1.f / fmaxf(sqrtf(ss), 1e-12f);
    float k1 = a * inv * (kgam[h*DHC + lane]      + 1.f) * 8.0f;
    float k2 = b * inv * (kgam[h*DHC + lane + 32] + 1.f) * 8.0f;

    if (timeL) {
        int t = (tok / SC) % TC;
        float invf = expf(-(float)lane * (9.210340371976184f / 32.f));
        float th = (float)t * invf;
        float c = cosf(th), sn = sinf(th);
        kp[lane]      = k1*c - k2*sn;
        kp[lane + 32] = k2*c + k1*sn;
        float* qp = q + base;
        float q1 = qp[lane], q2 = qp[lane+32];
        qp[lane]      = q1*c - q2*sn;
        qp[lane + 32] = q2*c + q1*sn;
    } else {
        kp[lane]      = k1;
        kp[lane + 32] = k2;
    }

    float m = mix[(size_t)tok*HEADSC + h];
    float* vp = v + base;
    const float* rp = rv + base;
    float v1 = vp[lane], v2 = vp[lane+32];
    vp[lane]      = v1 + m * (rp[lane]      - v1);
    vp[lane + 32] = v2 + m * (rp[lane + 32] - v2);
}

// ---------------------------------------------------------------------------
// Space attention (single-pass softmax, analytic max 50). Output hi/lo fp16.
// ---------------------------------------------------------------------------
__global__ void __launch_bounds__(256) attn_space_kernel(
    const float* __restrict__ q, const float* __restrict__ k,
    const float* __restrict__ v, const float* __restrict__ gate,
    __half* __restrict__ oh, __half* __restrict__ ol)
{
    extern __shared__ float sm[];
    float* Ks = sm;
    float* Vs = sm + SC*DHC;
    int seq = blockIdx.x;
    int h = blockIdx.y;
    int base = seq * SC;
    int tid = threadIdx.x;

    for (int idx = tid; idx < SC*DHC; idx += 256) {
        int row = idx >> 6, d = idx & 63;
        size_t g = (size_t)(base + row)*DIMC + h*DHC + d;
        Ks[idx] = k[g];
        Vs[idx] = v[g];
    }
    __syncthreads();

    size_t qoff = (size_t)(base + tid)*DIMC + h*DHC;
    float4 qr[16];
    const float4* qp = reinterpret_cast<const float4*>(q + qoff);
    #pragma unroll
    for (int i = 0; i < 16; i++) qr[i] = qp[i];

    float acc[DHC];
    #pragma unroll
    for (int d = 0; d < DHC; d++) acc[d] = 0.f;
    float l = 0.f;
    for (int j = 0; j < SC; j++) {
        const float4* kj = reinterpret_cast<const float4*>(Ks + j*DHC);
        float s = 0.f;
        #pragma unroll
        for (int i = 0; i < 16; i++) {
            float4 kk = kj[i];
            s = fmaf(qr[i].x, kk.x, s); s = fmaf(qr[i].y, kk.y, s);
            s = fmaf(qr[i].z, kk.z, s); s = fmaf(qr[i].w, kk.w, s);
        }
        s = 50.f * __tanhf(s * (0.125f * 0.02f));
        float p = __expf(s - 50.f);
        l += p;
        const float4* vj = reinterpret_cast<const float4*>(Vs + j*DHC);
        #pragma unroll
        for (int i = 0; i < 16; i++) {
            float4 vv = vj[i];
            acc[i*4+0] = fmaf(p, vv.x, acc[i*4+0]);
            acc[i*4+1] = fmaf(p, vv.y, acc[i*4+1]);
            acc[i*4+2] = fmaf(p, vv.z, acc[i*4+2]);
            acc[i*4+3] = fmaf(p, vv.w, acc[i*4+3]);
        }
    }
    float gs = gate[(size_t)(base + tid)*HEADSC + h] / l;
    #pragma unroll
    for (int d = 0; d < DHC; d++) {
        float val = acc[d] * gs;
        __half hh, hl;
        split2(val, hh, hl);
        oh[qoff + d] = hh; ol[qoff + d] = hl;
    }
}

// ---------------------------------------------------------------------------
// Time attention (causal, len 32). One warp per (b*S+s, head). Output hi/lo.
// ---------------------------------------------------------------------------
__global__ void attn_time_kernel(
    const float* __restrict__ q, const float* __restrict__ k,
    const float* __restrict__ v, const float* __restrict__ gate,
    __half* __restrict__ oh, __half* __restrict__ ol)
{
    __shared__ float Ks[TC*DHC];
    __shared__ float Vs[TC*DHC];
    int bs = blockIdx.x;
    int h = blockIdx.y;
    int b = bs / SC, s = bs % SC;
    int tokBase = b*TC*SC + s;
    int lane = threadIdx.x;

    for (int idx = lane; idx < TC*DHC; idx += 32) {
        int row = idx >> 6, d = idx & 63;
        size_t g = (size_t)(tokBase + row*SC)*DIMC + h*DHC + d;
        Ks[idx] = k[g];
        Vs[idx] = v[g];
    }
    __syncwarp();

    int tok = tokBase + lane*SC;
    size_t qoff = (size_t)tok*DIMC + h*DHC;
    float4 qr[16];
    const float4* qp = reinterpret_cast<const float4*>(q + qoff);
    #pragma unroll
    for (int i = 0; i < 16; i++) qr[i] = qp[i];

    float acc[DHC];
    #pragma unroll
    for (int d = 0; d < DHC; d++) acc[d] = 0.f;
    float l = 0.f;
    for (int j = 0; j <= lane; j++) {
        const float4* kj = reinterpret_cast<const float4*>(Ks + j*DHC);
        float sc = 0.f;
        #pragma unroll
        for (int i = 0; i < 16; i++) {
            float4 kk = kj[i];
            sc = fmaf(qr[i].x, kk.x, sc); sc = fmaf(qr[i].y, kk.y, sc);
            sc = fmaf(qr[i].z, kk.z, sc); sc = fmaf(qr[i].w, kk.w, sc);
        }
        sc = 50.f * __tanhf(sc * (0.125f * 0.02f));
        float p = __expf(sc - 50.f);
        l += p;
        const float4* vj = reinterpret_cast<const float4*>(Vs + j*DHC);
        #pragma unroll
        for (int i = 0; i < 16; i++) {
            float4 vv = vj[i];
            acc[i*4+0] = fmaf(p, vv.x, acc[i*4+0]);
            acc[i*4+1] = fmaf(p, vv.y, acc[i*4+1]);
            acc[i*4+2] = fmaf(p, vv.z, acc[i*4+2]);
            acc[i*4+3] = fmaf(p, vv.w, acc[i*4+3]);
        }
    }
    float gs = gate[(size_t)tok*HEADSC + h] / l;
    #pragma unroll
    for (int d = 0; d < DHC; d++) {
        float val = acc[d] * gs;
        __half hh, hl;
        split2(val, hh, hl);
        oh[qoff + d] = hh; ol[qoff + d] = hl;
    }
}

// ---------------------------------------------------------------------------
// act = h_a * gelu_exact(h_g), output hi/lo fp16
// ---------------------------------------------------------------------------
__global__ void gelumul_kernel(const float* __restrict__ h,
                               __half* __restrict__ acth,
                               __half* __restrict__ actl)
{
    int idx = blockIdx.x * 256 + threadIdx.x;    // NTOK*DFF total
    int m = idx / DFFC;
    int j = idx - m * DFFC;
    float a = h[(size_t)m*2*DFFC + j];
    float g = h[(size_t)m*2*DFFC + DFFC + j];
    float gl = 0.5f * g * (1.f + erff(g * 0.70710678118654752f));
    __half hh, hl;
    split2(a * gl, hh, hl);
    acth[idx] = hh; actl[idx] = hl;
}

// ---------------------------------------------------------------------------
// Orchestration
// ---------------------------------------------------------------------------
extern "C" void kernel_launch(void* const* d_in, const int* in_sizes, int n_in,
                              void* d_out, int out_size)
{
    (void)in_sizes; (void)n_in; (void)out_size;
    const float* tokens      = (const float*)d_in[0];
    const float* attn_norm_w = (const float*)d_in[1];
    const float* Wq          = (const float*)d_in[2];
    const float* Wk          = (const float*)d_in[3];
    const float* Wv          = (const float*)d_in[4];
    const float* Wo          = (const float*)d_in[5];
    const float* Wg          = (const float*)d_in[6];
    const float* Wmix        = (const float*)d_in[7];
    const float* bmix        = (const float*)d_in[8];
    const float* kgam        = (const float*)d_in[9];
    const float* ffnw        = (const float*)d_in[10];
    const float* Win         = (const float*)d_in[11];
    const float* b_in        = (const float*)d_in[12];
    const float* Wout        = (const float*)d_in[13];
    const float* b_out       = (const float*)d_in[14];
    const float* vrnw        = (const float*)d_in[15];
    const float* vrW         = (const float*)d_in[16];
    const float* fnw         = (const float*)d_in[17];
    float* out = (float*)d_out;

    float *x,*q,*k,*v,*rv,*h,*mix,*gate;
    __half *tnh,*tnl,*oh,*ol,*acth,*actl;
    __half *Wqh,*Wql,*Wkh,*Wkl,*Wvh,*Wvl,*Woh,*Wol,*Winh,*Winl,*Wouth,*Woutl,*vrWh,*vrWl;
    cudaGetSymbolAddress((void**)&x,   g_x);
    cudaGetSymbolAddress((void**)&q,   g_q);
    cudaGetSymbolAddress((void**)&k,   g_k);
    cudaGetSymbolAddress((void**)&v,   g_v);
    cudaGetSymbolAddress((void**)&rv,  g_rv);
    cudaGetSymbolAddress((void**)&h,   g_h);
    cudaGetSymbolAddress((void**)&mix, g_mix);
    cudaGetSymbolAddress((void**)&gate,g_gate);
    cudaGetSymbolAddress((void**)&tnh, g_tnh);
    cudaGetSymbolAddress((void**)&tnl, g_tnl);
    cudaGetSymbolAddress((void**)&oh,  g_oh);
    cudaGetSymbolAddress((void**)&ol,  g_ol);
    cudaGetSymbolAddress((void**)&acth,g_acth);
    cudaGetSymbolAddress((void**)&actl,g_actl);
    cudaGetSymbolAddress((void**)&Wqh, g_Wqh);  cudaGetSymbolAddress((void**)&Wql, g_Wql);
    cudaGetSymbolAddress((void**)&Wkh, g_Wkh);  cudaGetSymbolAddress((void**)&Wkl, g_Wkl);
    cudaGetSymbolAddress((void**)&Wvh, g_Wvh);  cudaGetSymbolAddress((void**)&Wvl, g_Wvl);
    cudaGetSymbolAddress((void**)&Woh, g_Woh2); cudaGetSymbolAddress((void**)&Wol, g_Wol2);
    cudaGetSymbolAddress((void**)&Winh,g_Winh); cudaGetSymbolAddress((void**)&Winl,g_Winl);
    cudaGetSymbolAddress((void**)&Wouth,g_Wouth); cudaGetSymbolAddress((void**)&Woutl,g_Woutl);
    cudaGetSymbolAddress((void**)&vrWh,g_vrWh); cudaGetSymbolAddress((void**)&vrWl,g_vrWl);

    cudaFuncSetAttribute(attn_space_kernel,
                         cudaFuncAttributeMaxDynamicSharedMemorySize, SMEM_SP);
    cudaFuncSetAttribute(hgemm_kernel,
                         cudaFuncAttributeMaxDynamicSharedMemorySize, HSMEM);
    cudaFuncSetAttribute(hgemm_qkv_kernel,
                         cudaFuncAttributeMaxDynamicSharedMemorySize, HSMEM);

    // x = tokens
    cudaMemcpyAsync(x, tokens, sizeof(float)*(size_t)NTOK*DIMC,
                    cudaMemcpyDeviceToDevice, 0);

    // decompose all weights once
    int nQ = DEPTHC*DIMC*DIMC, nIn = DEPTHC*DIMC*2*DFFC, nOut = DEPTHC*DFFC*DIMC;
    decomp_kernel<<<4096, 256>>>(Wq,  Wqh,  Wql,  nQ);
    decomp_kernel<<<4096, 256>>>(Wk,  Wkh,  Wkl,  nQ);
    decomp_kernel<<<4096, 256>>>(Wv,  Wvh,  Wvl,  nQ);
    decomp_kernel<<<4096, 256>>>(Wo,  Woh,  Wol,  nQ);
    decomp_kernel<<<4096, 256>>>(Win, Winh, Winl, nIn);
    decomp_kernel<<<4096, 256>>>(Wout,Wouth,Woutl,nOut);
    decomp_kernel<<<4096, 256>>>(vrW, vrWh, vrWl, DIMC*DIMC);

    dim3 g768(DIMC/128, NTOK/128);          // N=768 GEMMs
    dim3 gqkv(DIMC/128, NTOK/128, 3);       // fused QKV
    dim3 gffin(2*DFFC/128, NTOK/128);       // N=4096 GEMM

    // value residuals from original tokens
    rmsnorm_hl_kernel<<<NTOK, 256>>>(tokens, vrnw, tnh, tnl);
    hgemm_kernel<<<g768, 256, HSMEM>>>(tnh, tnl, vrWh, vrWl, rv, nullptr,
                                       DIMC, DIMC, 0);

    for (int i = 0; i < DEPTHC; i++) {
        size_t wOff = (size_t)i*DIMC*DIMC;
        // ---- attention sublayer ----
        rmsnorm_hl_kernel<<<NTOK, 256>>>(x, attn_norm_w + (size_t)i*DIMC, tnh, tnl);
        hgemm_qkv_kernel<<<gqkv, 256, HSMEM>>>(tnh, tnl,
                                               Wqh + wOff, Wql + wOff,
                                               Wkh + wOff, Wkl + wOff,
                                               Wvh + wOff, Wvl + wOff,
                                               q, k, v);
        mixgate_kernel<<<NTOK, 256>>>(tnh, tnl, Wmix + (size_t)i*DIMC*HEADSC,
                                      bmix + (size_t)i*HEADSC,
                                      Wg + (size_t)i*DIMC*HEADSC, mix, gate);

        bool timeL = (((i + 1) % 4) == 0);
        qkv_post_kernel<<<(NTOK*HEADSC)/8, 256>>>(q, k, v, rv, mix,
                                                  kgam + (size_t)i*HEADSC*DHC,
                                                  timeL ? 1 : 0);
        if (timeL) {
            attn_time_kernel<<<dim3(BC*SC, HEADSC), 32>>>(q, k, v, gate, oh, ol);
        } else {
            attn_space_kernel<<<dim3(BC*TC, HEADSC), 256, SMEM_SP>>>(q, k, v, gate, oh, ol);
        }
        // x += o @ Wo
        hgemm_kernel<<<g768, 256, HSMEM>>>(oh, ol, Woh + wOff, Wol + wOff,
                                           x, nullptr, DIMC, DIMC, 1);

        // ---- feedforward sublayer ----
        rmsnorm_hl_kernel<<<NTOK, 256>>>(x, ffnw + (size_t)i*DIMC, tnh, tnl);
        hgemm_kernel<<<gffin, 256, HSMEM>>>(tnh, tnl,
                                            Winh + (size_t)i*DIMC*2*DFFC,
                                            Winl + (size_t)i*DIMC*2*DFFC,
                                            h, b_in + (size_t)i*2*DFFC,
                                            2*DFFC, DIMC, 0);
        gelumul_kernel<<<(NTOK*DFFC)/256, 256>>>(h, acth, actl);
        // x += act @ Wout + b_out
        hgemm_kernel<<<g768, 256, HSMEM>>>(acth, actl,
                                           Wouth + (size_t)i*DFFC*DIMC,
                                           Woutl + (size_t)i*DFFC*DIMC,
                                           x, b_out + (size_t)i*DIMC,
                                           DIMC, DFFC, 1);
    }

    rmsnorm_kernel<<<NTOK, 256>>>(x, fnw, out);
}